// round 5
// baseline (speedup 1.0000x reference)
#include <cuda_runtime.h>
#include <cstdint>

#define NN 50000
#define EE 800000
#define DD 128

// ---------------- scratch (static device globals; no allocation allowed) ----
__device__ __align__(16) float g_q[NN * DD];
__device__ __align__(16) float g_k[NN * DD];
__device__ __align__(16) float g_v[NN * DD];
__device__ __align__(16) float g_skip[NN * DD];
__device__ __align__(16) float g_h[NN * DD];

__device__ __align__(16) int g_deg[NN];
__device__ __align__(16) int g_off[NN + 2];
__device__ __align__(16) int g_cursor[NN];
__device__ __align__(16) int g_bsum[128];
__device__ __align__(16) int g_boff[128];
__device__ __align__(16) int g_csrc[EE];
__device__ int g_is64;

// ---------------- fused: zero degree array + edge dtype detection -----------
// int64 edge_index => every odd int32 word of the first 1024 entries is the
// zero hi-word; int32 => random node ids, nonzero w.p. 1-1/50000 each.
__global__ void k_detect_zero(const int* __restrict__ p) {
    int i = blockIdx.x * blockDim.x + threadIdx.x;
    if (i < NN) g_deg[i] = 0;
    if (blockIdx.x == 0) {
        __shared__ int any;
        if (threadIdx.x == 0) any = 0;
        __syncthreads();
        int nz = 0;
        for (int t = threadIdx.x; t < 1024; t += blockDim.x) nz |= p[2 * t + 1];
        if (nz) any = 1;
        __syncthreads();
        if (threadIdx.x == 0) g_is64 = (any == 0);
    }
}

__device__ __forceinline__ int load_edge(const void* ei, long long idx) {
    int v;
    if (g_is64) v = (int)((const long long*)ei)[idx];
    else        v = ((const int*)ei)[idx];
    return min(max(v, 0), NN - 1);
}

// ---------------- CSR build -------------------------------------------------
__global__ void k_hist(const void* __restrict__ ei) {
    int e = blockIdx.x * blockDim.x + threadIdx.x;
    if (e < EE) atomicAdd(&g_deg[load_edge(ei, (long long)EE + e)], 1);
}

__global__ void k_scan1() {
    __shared__ int sh[512];
    int tid = threadIdx.x;
    int i = blockIdx.x * 512 + tid;
    int v = (i < NN) ? g_deg[i] : 0;
    sh[tid] = v;
    __syncthreads();
    for (int off = 1; off < 512; off <<= 1) {
        int t = 0;
        if (tid >= off) t = sh[tid - off];
        __syncthreads();
        sh[tid] += t;
        __syncthreads();
    }
    if (i < NN) g_off[i] = sh[tid] - v;
    if (tid == 511) g_bsum[blockIdx.x] = sh[511];
}

__global__ void k_scan2(int nb) {
    __shared__ int sh[128];
    int tid = threadIdx.x;
    int v = (tid < nb) ? g_bsum[tid] : 0;
    sh[tid] = v;
    __syncthreads();
    for (int off = 1; off < 128; off <<= 1) {
        int t = 0;
        if (tid >= off) t = sh[tid - off];
        __syncthreads();
        sh[tid] += t;
        __syncthreads();
    }
    g_boff[tid] = sh[tid] - v;
}

__global__ void k_scan3() {
    int i = blockIdx.x * blockDim.x + threadIdx.x;
    if (i < NN) {
        int o = g_off[i] + g_boff[i >> 9];
        g_off[i] = o;
        g_cursor[i] = o;
    }
    if (i == 0) g_off[NN] = EE;
}

__global__ void k_scatter(const void* __restrict__ ei) {
    int e = blockIdx.x * blockDim.x + threadIdx.x;
    if (e < EE) {
        int dst = load_edge(ei, (long long)EE + e);
        int src = load_edge(ei, e);
        int pos = atomicAdd(&g_cursor[dst], 1);
        if (pos < EE) g_csrc[pos] = src;
    }
}

// ---------------- fused 4-way projection GEMM (x @ {Wq,Wk,Wv,Ws} + b) ------
// 256 threads, 32 rows/block. cp = tid&63 owns cols (2cp, 2cp+1); rg = tid>>6
// owns rows rg*8..rg*8+7. Matrix loop INSIDE the d-loop: each shared x value
// feeds 4 matrices. LDS.128 grabs 2 duplicated d-slots at once. Per d-pair:
// 8 LDS.128 + 8 LDG.64 + 64 FFMA2 -> ~73% FMA-pipe efficiency (f32x2 = 2x
// fp32 rate on sm_103a).
__global__ void __launch_bounds__(256) k_proj(
    const float* __restrict__ x_in,
    const float* __restrict__ w0, const float* __restrict__ b0,
    const float* __restrict__ w1, const float* __restrict__ b1,
    const float* __restrict__ w2, const float* __restrict__ b2,
    const float* __restrict__ w3, const float* __restrict__ b3)
{
    __shared__ float2 xs[32][DD];   // x duplicated into both halves; 32 KB

    const float* x = (x_in != nullptr) ? x_in : g_h;

    int tid = threadIdx.x;
    int row0 = blockIdx.x * 32;

    for (int i = tid; i < 32 * DD; i += 256) {
        int r = i >> 7, d = i & 127;
        int row = row0 + r;
        float v = (row < NN) ? x[row * DD + d] : 0.f;
        xs[r][d] = make_float2(v, v);
    }
    __syncthreads();

    int cp = tid & 63;
    int rbase = (tid >> 6) * 8;

    const float* Ws[4] = {w0, w1, w2, w3};
    const float* Bs[4] = {b0, b1, b2, b3};

    unsigned long long acc[4][8];
#pragma unroll
    for (int m = 0; m < 4; m++) {
        float2 bb = *(const float2*)(Bs[m] + 2 * cp);
        unsigned long long bp;
        asm("mov.b64 %0, {%1, %2};" : "=l"(bp) : "f"(bb.x), "f"(bb.y));
#pragma unroll
        for (int r = 0; r < 8; r++) acc[m][r] = bp;
    }

#pragma unroll 2
    for (int d = 0; d < DD; d += 2) {
        unsigned long long w[4][2];
#pragma unroll
        for (int m = 0; m < 4; m++) {
            float2 wa = *(const float2*)(Ws[m] + d * DD + 2 * cp);
            float2 wb = *(const float2*)(Ws[m] + (d + 1) * DD + 2 * cp);
            asm("mov.b64 %0, {%1, %2};" : "=l"(w[m][0]) : "f"(wa.x), "f"(wa.y));
            asm("mov.b64 %0, {%1, %2};" : "=l"(w[m][1]) : "f"(wb.x), "f"(wb.y));
        }
#pragma unroll
        for (int r = 0; r < 8; r++) {
            float4 a4 = *(const float4*)(&xs[rbase + r][d]);   // LDS.128: (xd,xd,xd1,xd1)
            unsigned long long a0, a1;
            asm("mov.b64 %0, {%1, %2};" : "=l"(a0) : "f"(a4.x), "f"(a4.y));
            asm("mov.b64 %0, {%1, %2};" : "=l"(a1) : "f"(a4.z), "f"(a4.w));
#pragma unroll
            for (int m = 0; m < 4; m++) {
                asm("fma.rn.f32x2 %0, %1, %2, %0;" : "+l"(acc[m][r]) : "l"(a0), "l"(w[m][0]));
                asm("fma.rn.f32x2 %0, %1, %2, %0;" : "+l"(acc[m][r]) : "l"(a1), "l"(w[m][1]));
            }
        }
    }

    float* Os[4] = {g_q, g_k, g_v, g_skip};
#pragma unroll
    for (int m = 0; m < 4; m++) {
        float* O = Os[m];
#pragma unroll
        for (int r = 0; r < 8; r++) {
            int row = row0 + rbase + r;
            if (row < NN)
                *reinterpret_cast<float2*>(O + row * DD + 2 * cp) =
                    *reinterpret_cast<float2*>(&acc[m][r]);
        }
    }
}

// ---------------- warp-per-node online-softmax attention + skip ------------
// 2 edges per iteration: two independent gather+dot+shfl chains, merged into
// one online-softmax update (halves the serial latency per edge).
__global__ void __launch_bounds__(256) k_attn(float* out_ptr) {
    int node = (blockIdx.x * blockDim.x + threadIdx.x) >> 5;
    if (node >= NN) return;
    int lane = threadIdx.x & 31;

    int do_relu = (out_ptr == nullptr);
    float* out = do_relu ? g_h : out_ptr;

    const float4 q4 = *(const float4*)(g_q + node * DD + lane * 4);

    float4 acc = make_float4(0.f, 0.f, 0.f, 0.f);
    float m = -1e30f, s = 0.f;

    int j = g_off[node];
    int end = g_off[node + 1];
    const float SC = 0.17677669529663689f;       // 1/sqrt(32)

    for (; j + 2 <= end; j += 2) {
        int s0 = g_csrc[j];
        int s1 = g_csrc[j + 1];
        const float4 k0 = *(const float4*)(g_k + s0 * DD + lane * 4);
        const float4 v0 = *(const float4*)(g_v + s0 * DD + lane * 4);
        const float4 k1 = *(const float4*)(g_k + s1 * DD + lane * 4);
        const float4 v1 = *(const float4*)(g_v + s1 * DD + lane * 4);

        float t0 = q4.x * k0.x + q4.y * k0.y + q4.z * k0.z + q4.w * k0.w;
        float t1 = q4.x * k1.x + q4.y * k1.y + q4.z * k1.z + q4.w * k1.w;
        t0 += __shfl_xor_sync(0xffffffffu, t0, 1);
        t1 += __shfl_xor_sync(0xffffffffu, t1, 1);
        t0 += __shfl_xor_sync(0xffffffffu, t0, 2);
        t1 += __shfl_xor_sync(0xffffffffu, t1, 2);
        t0 += __shfl_xor_sync(0xffffffffu, t0, 4);
        t1 += __shfl_xor_sync(0xffffffffu, t1, 4);

        float l0 = t0 * SC;
        float l1 = t1 * SC;
        float nm = fmaxf(m, fmaxf(l0, l1));
        float fac = __expf(m - nm);
        float e0 = __expf(l0 - nm);
        float e1 = __expf(l1 - nm);
        s = s * fac + e0 + e1;
        acc.x = acc.x * fac + v0.x * e0 + v1.x * e1;
        acc.y = acc.y * fac + v0.y * e0 + v1.y * e1;
        acc.z = acc.z * fac + v0.z * e0 + v1.z * e1;
        acc.w = acc.w * fac + v0.w * e0 + v1.w * e1;
        m = nm;
    }
    if (j < end) {
        int s0 = g_csrc[j];
        const float4 k0 = *(const float4*)(g_k + s0 * DD + lane * 4);
        const float4 v0 = *(const float4*)(g_v + s0 * DD + lane * 4);
        float t0 = q4.x * k0.x + q4.y * k0.y + q4.z * k0.z + q4.w * k0.w;
        t0 += __shfl_xor_sync(0xffffffffu, t0, 1);
        t0 += __shfl_xor_sync(0xffffffffu, t0, 2);
        t0 += __shfl_xor_sync(0xffffffffu, t0, 4);
        float l0 = t0 * SC;
        float nm = fmaxf(m, l0);
        float fac = __expf(m - nm);
        float e0 = __expf(l0 - nm);
        s = s * fac + e0;
        acc.x = acc.x * fac + v0.x * e0;
        acc.y = acc.y * fac + v0.y * e0;
        acc.z = acc.z * fac + v0.z * e0;
        acc.w = acc.w * fac + v0.w * e0;
        m = nm;
    }

    float inv = 1.f / (s + 1e-16f);
    const float4 sk = *(const float4*)(g_skip + node * DD + lane * 4);
    float4 o;
    o.x = acc.x * inv + sk.x;
    o.y = acc.y * inv + sk.y;
    o.z = acc.z * inv + sk.z;
    o.w = acc.w * inv + sk.w;
    if (do_relu) {
        o.x = fmaxf(o.x, 0.f);
        o.y = fmaxf(o.y, 0.f);
        o.z = fmaxf(o.z, 0.f);
        o.w = fmaxf(o.w, 0.f);
    }
    *(float4*)(out + node * DD + lane * 4) = o;
}

// ---------------- launch ----------------------------------------------------
extern "C" void kernel_launch(void* const* d_in, const int* in_sizes, int n_in,
                              void* d_out, int out_size) {
    const float* x = (const float*)d_in[0];
    const void* ei = d_in[1];    // int32 or int64 — detected on device
    const float* L0[8];
    const float* L1[8];
    for (int i = 0; i < 8; i++) {
        L0[i] = (const float*)d_in[2 + i];
        L1[i] = (const float*)d_in[10 + i];
    }
    float* out = (float*)d_out;

    const int NB_SCAN1 = (NN + 511) / 512;       // 98
    const int PROJ_GRID = (NN + 31) / 32;        // 1563
    const int ATTN_GRID = (NN + 7) / 8;          // 6250

    // launch index 3 = k_proj layer 0 (the slot ncu captured last round)
    k_detect_zero<<<(NN + 255) / 256, 256>>>((const int*)ei);      // 0
    k_hist<<<(EE + 255) / 256, 256>>>(ei);                         // 1
    k_scan1<<<NB_SCAN1, 512>>>();                                  // 2
    k_proj<<<PROJ_GRID, 256>>>(x,                                  // 3 (profiled)
        L0[0], L0[1], L0[2], L0[3], L0[4], L0[5], L0[6], L0[7]);
    k_scan2<<<1, 128>>>(NB_SCAN1);                                 // 4
    k_scan3<<<(NN + 255) / 256, 256>>>();                          // 5
    k_scatter<<<(EE + 255) / 256, 256>>>(ei);                      // 6
    k_attn<<<ATTN_GRID, 256>>>(nullptr);                           // 7: g_h + relu
    k_proj<<<PROJ_GRID, 256>>>(nullptr,                            // 8
        L1[0], L1[1], L1[2], L1[3], L1[4], L1[5], L1[6], L1[7]);
    k_attn<<<ATTN_GRID, 256>>>(out);                               // 9
}

// round 6
// speedup vs baseline: 2.4484x; 2.4484x over previous
#include <cuda_runtime.h>
#include <cstdint>

#define NN 50000
#define EE 800000
#define DD 128

// ---------------- scratch (static device globals; no allocation allowed) ----
__device__ __align__(16) float g_q[NN * DD];
__device__ __align__(16) float g_k[NN * DD];
__device__ __align__(16) float g_v[NN * DD];
__device__ __align__(16) float g_skip[NN * DD];
__device__ __align__(16) float g_h[NN * DD];

__device__ __align__(16) unsigned g_wt[8 * DD * DD];   // tf32(rna) weights

__device__ __align__(16) int g_deg[NN];
__device__ __align__(16) int g_off[NN + 2];
__device__ __align__(16) int g_cursor[NN];
__device__ __align__(16) int g_bsum[128];
__device__ __align__(16) int g_boff[128];
__device__ __align__(16) int g_csrc[EE];
__device__ int g_is64;

// ---------------- fused: zero degree array + edge dtype detection -----------
__global__ void k_detect_zero(const int* __restrict__ p) {
    int i = blockIdx.x * blockDim.x + threadIdx.x;
    if (i < NN) g_deg[i] = 0;
    if (blockIdx.x == 0) {
        __shared__ int any;
        if (threadIdx.x == 0) any = 0;
        __syncthreads();
        int nz = 0;
        for (int t = threadIdx.x; t < 1024; t += blockDim.x) nz |= p[2 * t + 1];
        if (nz) any = 1;
        __syncthreads();
        if (threadIdx.x == 0) g_is64 = (any == 0);
    }
}

__device__ __forceinline__ int load_edge(const void* ei, long long idx) {
    int v;
    if (g_is64) v = (int)((const long long*)ei)[idx];
    else        v = ((const int*)ei)[idx];
    return min(max(v, 0), NN - 1);
}

// ---------------- weight pre-conversion fp32 -> tf32(rna) -------------------
__global__ void k_wconv(
    const float* __restrict__ w0, const float* __restrict__ w1,
    const float* __restrict__ w2, const float* __restrict__ w3,
    const float* __restrict__ w4, const float* __restrict__ w5,
    const float* __restrict__ w6, const float* __restrict__ w7)
{
    int i = blockIdx.x * blockDim.x + threadIdx.x;     // 0 .. 131071
    int m = i >> 14;
    int off = i & 16383;
    const float* src =
        (m == 0) ? w0 : (m == 1) ? w1 : (m == 2) ? w2 : (m == 3) ? w3 :
        (m == 4) ? w4 : (m == 5) ? w5 : (m == 6) ? w6 : w7;
    float f = src[off];
    unsigned u;
    asm("cvt.rna.tf32.f32 %0, %1;" : "=r"(u) : "f"(f));
    g_wt[i] = u;
}

// ---------------- CSR build -------------------------------------------------
__global__ void k_hist(const void* __restrict__ ei) {
    int e = blockIdx.x * blockDim.x + threadIdx.x;
    if (e < EE) atomicAdd(&g_deg[load_edge(ei, (long long)EE + e)], 1);
}

__global__ void k_scan1() {
    __shared__ int sh[512];
    int tid = threadIdx.x;
    int i = blockIdx.x * 512 + tid;
    int v = (i < NN) ? g_deg[i] : 0;
    sh[tid] = v;
    __syncthreads();
    for (int off = 1; off < 512; off <<= 1) {
        int t = 0;
        if (tid >= off) t = sh[tid - off];
        __syncthreads();
        sh[tid] += t;
        __syncthreads();
    }
    if (i < NN) g_off[i] = sh[tid] - v;
    if (tid == 511) g_bsum[blockIdx.x] = sh[511];
}

__global__ void k_scan2(int nb) {
    __shared__ int sh[128];
    int tid = threadIdx.x;
    int v = (tid < nb) ? g_bsum[tid] : 0;
    sh[tid] = v;
    __syncthreads();
    for (int off = 1; off < 128; off <<= 1) {
        int t = 0;
        if (tid >= off) t = sh[tid - off];
        __syncthreads();
        sh[tid] += t;
        __syncthreads();
    }
    g_boff[tid] = sh[tid] - v;
}

__global__ void k_scan3() {
    int i = blockIdx.x * blockDim.x + threadIdx.x;
    if (i < NN) {
        int o = g_off[i] + g_boff[i >> 9];
        g_off[i] = o;
        g_cursor[i] = o;
    }
    if (i == 0) g_off[NN] = EE;
}

__global__ void k_scatter(const void* __restrict__ ei) {
    int e = blockIdx.x * blockDim.x + threadIdx.x;
    if (e < EE) {
        int dst = load_edge(ei, (long long)EE + e);
        int src = load_edge(ei, e);
        int pos = atomicAdd(&g_cursor[dst], 1);
        if (pos < EE) g_csrc[pos] = src;
    }
}

// ---------------- tensor-core projection GEMM (tf32 mma.sync) ---------------
// 128 threads / 4 warps, M-tile 64. Warp w computes rows [w*16, w*16+16) x
// all 128 cols, for each of the 4 matrices sequentially (m-loop rolled).
// A-frags: padded smem (stride 132 -> conflict-free). B-frags: LDG from
// L2-resident pre-converted tf32 weights. acc in fp32 (64 regs).
// x_in == nullptr -> read g_h. wbase: 0 (layer 0) or 4 (layer 1).
__global__ void __launch_bounds__(128) k_proj(
    const float* __restrict__ x_in, int wbase,
    const float* __restrict__ bq, const float* __restrict__ bk,
    const float* __restrict__ bv, const float* __restrict__ bs)
{
    __shared__ unsigned xs[64][132];           // tf32 bits, padded stride

    const float* x = (x_in != nullptr) ? x_in : g_h;
    int tid = threadIdx.x;
    int row0 = blockIdx.x * 64;

    for (int i = tid; i < 64 * 32; i += 128) { // 32 float4 per row
        int r = i >> 5, c = (i & 31) * 4;
        float4 v = make_float4(0.f, 0.f, 0.f, 0.f);
        int row = row0 + r;
        if (row < NN) v = *(const float4*)(x + row * DD + c);
        unsigned u0, u1, u2, u3;
        asm("cvt.rna.tf32.f32 %0, %1;" : "=r"(u0) : "f"(v.x));
        asm("cvt.rna.tf32.f32 %0, %1;" : "=r"(u1) : "f"(v.y));
        asm("cvt.rna.tf32.f32 %0, %1;" : "=r"(u2) : "f"(v.z));
        asm("cvt.rna.tf32.f32 %0, %1;" : "=r"(u3) : "f"(v.w));
        uint4 pk = make_uint4(u0, u1, u2, u3);
        *(uint4*)(&xs[r][c]) = pk;
    }
    __syncthreads();

    int warp = tid >> 5, lane = tid & 31;
    int gid = lane >> 2, tig = lane & 3;       // groupID, thread-in-group
    int rA = warp * 16 + gid;                  // local row for a0/a2

    for (int m = 0; m < 4; m++) {
        const unsigned* W = g_wt + (wbase + m) * (DD * DD);
        const float* B = (m == 0) ? bq : (m == 1) ? bk : (m == 2) ? bv : bs;
        float* O = (m == 0) ? g_q : (m == 1) ? g_k : (m == 2) ? g_v : g_skip;

        float acc[16][4];
#pragma unroll
        for (int nf = 0; nf < 16; nf++) {
            float2 bb = *(const float2*)(B + nf * 8 + 2 * tig);
            acc[nf][0] = bb.x; acc[nf][1] = bb.y;
            acc[nf][2] = bb.x; acc[nf][3] = bb.y;
        }

#pragma unroll 4
        for (int k0 = 0; k0 < DD; k0 += 8) {
            unsigned a0 = xs[rA][k0 + tig];
            unsigned a1 = xs[rA + 8][k0 + tig];
            unsigned a2 = xs[rA][k0 + tig + 4];
            unsigned a3 = xs[rA + 8][k0 + tig + 4];
            const unsigned* wk = W + (k0 + tig) * DD + gid;
#pragma unroll
            for (int nf = 0; nf < 16; nf++) {
                unsigned b0 = wk[nf * 8];
                unsigned b1 = wk[nf * 8 + 4 * DD];
                asm volatile(
                    "mma.sync.aligned.m16n8k8.row.col.f32.tf32.tf32.f32 "
                    "{%0,%1,%2,%3}, {%4,%5,%6,%7}, {%8,%9}, {%0,%1,%2,%3};\n"
                    : "+f"(acc[nf][0]), "+f"(acc[nf][1]),
                      "+f"(acc[nf][2]), "+f"(acc[nf][3])
                    : "r"(a0), "r"(a1), "r"(a2), "r"(a3), "r"(b0), "r"(b1));
            }
        }

        int rg = row0 + rA;
#pragma unroll
        for (int nf = 0; nf < 16; nf++) {
            if (rg < NN)
                *(float2*)(O + rg * DD + nf * 8 + 2 * tig) =
                    make_float2(acc[nf][0], acc[nf][1]);
            if (rg + 8 < NN)
                *(float2*)(O + (rg + 8) * DD + nf * 8 + 2 * tig) =
                    make_float2(acc[nf][2], acc[nf][3]);
        }
    }
}

// ---------------- warp-per-node online-softmax attention + skip ------------
__global__ void __launch_bounds__(256) k_attn(float* out_ptr) {
    int node = (blockIdx.x * blockDim.x + threadIdx.x) >> 5;
    if (node >= NN) return;
    int lane = threadIdx.x & 31;

    int do_relu = (out_ptr == nullptr);
    float* out = do_relu ? g_h : out_ptr;

    const float4 q4 = *(const float4*)(g_q + node * DD + lane * 4);

    float4 acc = make_float4(0.f, 0.f, 0.f, 0.f);
    float m = -1e30f, s = 0.f;

    int j = g_off[node];
    int end = g_off[node + 1];
    const float SC = 0.17677669529663689f;       // 1/sqrt(32)

    for (; j + 2 <= end; j += 2) {
        int s0 = g_csrc[j];
        int s1 = g_csrc[j + 1];
        const float4 k0 = *(const float4*)(g_k + s0 * DD + lane * 4);
        const float4 v0 = *(const float4*)(g_v + s0 * DD + lane * 4);
        const float4 k1 = *(const float4*)(g_k + s1 * DD + lane * 4);
        const float4 v1 = *(const float4*)(g_v + s1 * DD + lane * 4);

        float t0 = q4.x * k0.x + q4.y * k0.y + q4.z * k0.z + q4.w * k0.w;
        float t1 = q4.x * k1.x + q4.y * k1.y + q4.z * k1.z + q4.w * k1.w;
        t0 += __shfl_xor_sync(0xffffffffu, t0, 1);
        t1 += __shfl_xor_sync(0xffffffffu, t1, 1);
        t0 += __shfl_xor_sync(0xffffffffu, t0, 2);
        t1 += __shfl_xor_sync(0xffffffffu, t1, 2);
        t0 += __shfl_xor_sync(0xffffffffu, t0, 4);
        t1 += __shfl_xor_sync(0xffffffffu, t1, 4);

        float l0 = t0 * SC;
        float l1 = t1 * SC;
        float nm = fmaxf(m, fmaxf(l0, l1));
        float fac = __expf(m - nm);
        float e0 = __expf(l0 - nm);
        float e1 = __expf(l1 - nm);
        s = s * fac + e0 + e1;
        acc.x = acc.x * fac + v0.x * e0 + v1.x * e1;
        acc.y = acc.y * fac + v0.y * e0 + v1.y * e1;
        acc.z = acc.z * fac + v0.z * e0 + v1.z * e1;
        acc.w = acc.w * fac + v0.w * e0 + v1.w * e1;
        m = nm;
    }
    if (j < end) {
        int s0 = g_csrc[j];
        const float4 k0 = *(const float4*)(g_k + s0 * DD + lane * 4);
        const float4 v0 = *(const float4*)(g_v + s0 * DD + lane * 4);
        float t0 = q4.x * k0.x + q4.y * k0.y + q4.z * k0.z + q4.w * k0.w;
        t0 += __shfl_xor_sync(0xffffffffu, t0, 1);
        t0 += __shfl_xor_sync(0xffffffffu, t0, 2);
        t0 += __shfl_xor_sync(0xffffffffu, t0, 4);
        float l0 = t0 * SC;
        float nm = fmaxf(m, l0);
        float fac = __expf(m - nm);
        float e0 = __expf(l0 - nm);
        s = s * fac + e0;
        acc.x = acc.x * fac + v0.x * e0;
        acc.y = acc.y * fac + v0.y * e0;
        acc.z = acc.z * fac + v0.z * e0;
        acc.w = acc.w * fac + v0.w * e0;
        m = nm;
    }

    float inv = 1.f / (s + 1e-16f);
    const float4 sk = *(const float4*)(g_skip + node * DD + lane * 4);
    float4 o;
    o.x = acc.x * inv + sk.x;
    o.y = acc.y * inv + sk.y;
    o.z = acc.z * inv + sk.z;
    o.w = acc.w * inv + sk.w;
    if (do_relu) {
        o.x = fmaxf(o.x, 0.f);
        o.y = fmaxf(o.y, 0.f);
        o.z = fmaxf(o.z, 0.f);
        o.w = fmaxf(o.w, 0.f);
    }
    *(float4*)(out + node * DD + lane * 4) = o;
}

// ---------------- launch ----------------------------------------------------
extern "C" void kernel_launch(void* const* d_in, const int* in_sizes, int n_in,
                              void* d_out, int out_size) {
    const float* x = (const float*)d_in[0];
    const void* ei = d_in[1];    // int32 or int64 — detected on device
    // per layer order: qw,qb,kw,kb,vw,vb,sw,sb
    float* out = (float*)d_out;

    const int NB_SCAN1 = (NN + 511) / 512;       // 98
    const int PROJ_GRID = (NN + 63) / 64;        // 782
    const int ATTN_GRID = (NN + 7) / 8;          // 6250

    k_detect_zero<<<(NN + 255) / 256, 256>>>((const int*)ei);      // 0
    k_wconv<<<512, 256>>>(                                         // 1
        (const float*)d_in[2], (const float*)d_in[4],
        (const float*)d_in[6], (const float*)d_in[8],
        (const float*)d_in[10], (const float*)d_in[12],
        (const float*)d_in[14], (const float*)d_in[16]);
    k_hist<<<(EE + 255) / 256, 256>>>(ei);                         // 2
    k_proj<<<PROJ_GRID, 128>>>(x, 0,                               // 3 (profiled)
        (const float*)d_in[3], (const float*)d_in[5],
        (const float*)d_in[7], (const float*)d_in[9]);
    k_scan1<<<NB_SCAN1, 512>>>();                                  // 4
    k_scan2<<<1, 128>>>(NB_SCAN1);                                 // 5
    k_scan3<<<(NN + 255) / 256, 256>>>();                          // 6
    k_scatter<<<(EE + 255) / 256, 256>>>(ei);                      // 7
    k_attn<<<ATTN_GRID, 256>>>(nullptr);                           // 8: g_h + relu
    k_proj<<<PROJ_GRID, 128>>>(nullptr, 4,                         // 9
        (const float*)d_in[11], (const float*)d_in[13],
        (const float*)d_in[15], (const float*)d_in[17]);
    k_attn<<<ATTN_GRID, 256>>>(out);                               // 10
}

// round 7
// speedup vs baseline: 3.6005x; 1.4706x over previous
#include <cuda_runtime.h>
#include <cstdint>

#define NN 50000
#define EE 800000
#define DD 128

// ---------------- scratch (static device globals; no allocation allowed) ----
__device__ __align__(16) float g_q[NN * DD];
__device__ __align__(16) float g_k[NN * DD];
__device__ __align__(16) float g_v[NN * DD];
__device__ __align__(16) float g_skip[NN * DD];
__device__ __align__(16) float g_h[NN * DD];

// tf32 weights, REPACKED into per-thread mma fragment order (see k_wrepack)
__device__ __align__(16) unsigned g_wt[8 * DD * DD];

__device__ __align__(16) int g_deg[NN];
__device__ __align__(16) int g_off[NN + 2];
__device__ __align__(16) int g_cursor[NN];
__device__ __align__(16) int g_bsum[128];
__device__ __align__(16) int g_boff[128];
__device__ __align__(16) int g_csrc[EE];
__device__ int g_is64;

// ---------------- fused: zero degree array + edge dtype detection -----------
__global__ void k_detect_zero(const int* __restrict__ p) {
    int i = blockIdx.x * blockDim.x + threadIdx.x;
    if (i < NN) g_deg[i] = 0;
    if (blockIdx.x == 0) {
        __shared__ int any;
        if (threadIdx.x == 0) any = 0;
        __syncthreads();
        int nz = 0;
        for (int t = threadIdx.x; t < 1024; t += blockDim.x) nz |= p[2 * t + 1];
        if (nz) any = 1;
        __syncthreads();
        if (threadIdx.x == 0) g_is64 = (any == 0);
    }
}

__device__ __forceinline__ int load_edge(const void* ei, long long idx) {
    int v;
    if (g_is64) v = (int)((const long long*)ei)[idx];
    else        v = ((const int*)ei)[idx];
    return min(max(v, 0), NN - 1);
}

// ---------------- weight conversion + fragment repack ------------------------
// Packed word index within one matrix: t = ((k0g*8 + j)*32 + lane)*4 + c
//   lane = gid*4 + tig (mma lane decomposition)
//   j<4:  b0 for nf = j*4 + c      -> W[k0g*8 + tig][ (j*4+c)*8 + gid ]
//   j>=4: b1 for nf = (j-4)*4 + c  -> W[k0g*8 + tig + 4][ ((j-4)*4+c)*8 + gid ]
// Consumption in k_proj: u[j] = ((uint4*)Wp)[(k0g*8 + j)*32 + lane] — one
// fully-coalesced 512B LDG.128 per (j, warp).
__global__ void k_wrepack(
    const float* __restrict__ w0, const float* __restrict__ w1,
    const float* __restrict__ w2, const float* __restrict__ w3,
    const float* __restrict__ w4, const float* __restrict__ w5,
    const float* __restrict__ w6, const float* __restrict__ w7)
{
    int i = blockIdx.x * blockDim.x + threadIdx.x;     // 0 .. 131071
    int m = i >> 14;
    int t = i & 16383;
    int c = t & 3;
    int lane = (t >> 2) & 31;
    int j = (t >> 7) & 7;
    int k0g = t >> 10;
    int gid = lane >> 2, tig = lane & 3;
    int nf = (j & 3) * 4 + c;
    int k = k0g * 8 + tig + ((j >= 4) ? 4 : 0);
    int n = nf * 8 + gid;
    const float* src =
        (m == 0) ? w0 : (m == 1) ? w1 : (m == 2) ? w2 : (m == 3) ? w3 :
        (m == 4) ? w4 : (m == 5) ? w5 : (m == 6) ? w6 : w7;
    float f = src[k * DD + n];
    unsigned u;
    asm("cvt.rna.tf32.f32 %0, %1;" : "=r"(u) : "f"(f));
    g_wt[i] = u;
}

// ---------------- CSR build -------------------------------------------------
__global__ void k_hist(const void* __restrict__ ei) {
    int e = blockIdx.x * blockDim.x + threadIdx.x;
    if (e < EE) atomicAdd(&g_deg[load_edge(ei, (long long)EE + e)], 1);
}

__global__ void k_scan1() {
    __shared__ int sh[512];
    int tid = threadIdx.x;
    int i = blockIdx.x * 512 + tid;
    int v = (i < NN) ? g_deg[i] : 0;
    sh[tid] = v;
    __syncthreads();
    for (int off = 1; off < 512; off <<= 1) {
        int t = 0;
        if (tid >= off) t = sh[tid - off];
        __syncthreads();
        sh[tid] += t;
        __syncthreads();
    }
    if (i < NN) g_off[i] = sh[tid] - v;
    if (tid == 511) g_bsum[blockIdx.x] = sh[511];
}

__global__ void k_scan2(int nb) {
    __shared__ int sh[128];
    int tid = threadIdx.x;
    int v = (tid < nb) ? g_bsum[tid] : 0;
    sh[tid] = v;
    __syncthreads();
    for (int off = 1; off < 128; off <<= 1) {
        int t = 0;
        if (tid >= off) t = sh[tid - off];
        __syncthreads();
        sh[tid] += t;
        __syncthreads();
    }
    g_boff[tid] = sh[tid] - v;
}

__global__ void k_scan3() {
    int i = blockIdx.x * blockDim.x + threadIdx.x;
    if (i < NN) {
        int o = g_off[i] + g_boff[i >> 9];
        g_off[i] = o;
        g_cursor[i] = o;
    }
    if (i == 0) g_off[NN] = EE;
}

__global__ void k_scatter(const void* __restrict__ ei) {
    int e = blockIdx.x * blockDim.x + threadIdx.x;
    if (e < EE) {
        int dst = load_edge(ei, (long long)EE + e);
        int src = load_edge(ei, e);
        int pos = atomicAdd(&g_cursor[dst], 1);
        if (pos < EE) g_csrc[pos] = src;
    }
}

// ---------------- tensor-core projection GEMM (tf32 mma.sync) ---------------
// 128 threads / 4 warps, M-tile 64. Warp w: rows [w*16, w*16+16) x 128 cols,
// 4 matrices sequentially. B-frags: 8x LDG.128 per k-group from repacked
// weights (fully coalesced). A-frags: padded smem. k-loop fully unrolled so
// ptxas front-batches the loads (high MLP).
__global__ void __launch_bounds__(128) k_proj(
    const float* __restrict__ x_in, int wbase,
    const float* __restrict__ bq, const float* __restrict__ bk,
    const float* __restrict__ bv, const float* __restrict__ bs)
{
    __shared__ unsigned xs[64][132];           // tf32 bits, padded stride

    const float* x = (x_in != nullptr) ? x_in : g_h;
    int tid = threadIdx.x;
    int row0 = blockIdx.x * 64;

    for (int i = tid; i < 64 * 32; i += 128) { // 32 float4 per row
        int r = i >> 5, c = (i & 31) * 4;
        float4 v = make_float4(0.f, 0.f, 0.f, 0.f);
        int row = row0 + r;
        if (row < NN) v = *(const float4*)(x + row * DD + c);
        unsigned u0, u1, u2, u3;
        asm("cvt.rna.tf32.f32 %0, %1;" : "=r"(u0) : "f"(v.x));
        asm("cvt.rna.tf32.f32 %0, %1;" : "=r"(u1) : "f"(v.y));
        asm("cvt.rna.tf32.f32 %0, %1;" : "=r"(u2) : "f"(v.z));
        asm("cvt.rna.tf32.f32 %0, %1;" : "=r"(u3) : "f"(v.w));
        *(uint4*)(&xs[r][c]) = make_uint4(u0, u1, u2, u3);
    }
    __syncthreads();

    int warp = tid >> 5, lane = tid & 31;
    int gid = lane >> 2, tig = lane & 3;
    int rA = warp * 16 + gid;

    for (int m = 0; m < 4; m++) {
        const uint4* Wp = (const uint4*)(g_wt + (wbase + m) * (DD * DD));
        const float* B = (m == 0) ? bq : (m == 1) ? bk : (m == 2) ? bv : bs;
        float* O = (m == 0) ? g_q : (m == 1) ? g_k : (m == 2) ? g_v : g_skip;

        float acc[16][4];
#pragma unroll
        for (int nf = 0; nf < 16; nf++) {
            float2 bb = *(const float2*)(B + nf * 8 + 2 * tig);
            acc[nf][0] = bb.x; acc[nf][1] = bb.y;
            acc[nf][2] = bb.x; acc[nf][3] = bb.y;
        }

#pragma unroll
        for (int k0g = 0; k0g < 16; k0g++) {
            uint4 u[8];
#pragma unroll
            for (int j = 0; j < 8; j++)
                u[j] = Wp[(k0g * 8 + j) * 32 + lane];

            int k0 = k0g * 8;
            unsigned a0 = xs[rA][k0 + tig];
            unsigned a1 = xs[rA + 8][k0 + tig];
            unsigned a2 = xs[rA][k0 + tig + 4];
            unsigned a3 = xs[rA + 8][k0 + tig + 4];

#pragma unroll
            for (int nf = 0; nf < 16; nf++) {
                int q = nf >> 2, cc = nf & 3;
                unsigned b0 = (cc == 0) ? u[q].x : (cc == 1) ? u[q].y
                            : (cc == 2) ? u[q].z : u[q].w;
                unsigned b1 = (cc == 0) ? u[4 + q].x : (cc == 1) ? u[4 + q].y
                            : (cc == 2) ? u[4 + q].z : u[4 + q].w;
                asm volatile(
                    "mma.sync.aligned.m16n8k8.row.col.f32.tf32.tf32.f32 "
                    "{%0,%1,%2,%3}, {%4,%5,%6,%7}, {%8,%9}, {%0,%1,%2,%3};\n"
                    : "+f"(acc[nf][0]), "+f"(acc[nf][1]),
                      "+f"(acc[nf][2]), "+f"(acc[nf][3])
                    : "r"(a0), "r"(a1), "r"(a2), "r"(a3), "r"(b0), "r"(b1));
            }
        }

        int rg = row0 + rA;
#pragma unroll
        for (int nf = 0; nf < 16; nf++) {
            if (rg < NN)
                *(float2*)(O + rg * DD + nf * 8 + 2 * tig) =
                    make_float2(acc[nf][0], acc[nf][1]);
            if (rg + 8 < NN)
                *(float2*)(O + (rg + 8) * DD + nf * 8 + 2 * tig) =
                    make_float2(acc[nf][2], acc[nf][3]);
        }
    }
}

// ---------------- warp-per-node online-softmax attention + skip ------------
__global__ void __launch_bounds__(256) k_attn(float* out_ptr) {
    int node = (blockIdx.x * blockDim.x + threadIdx.x) >> 5;
    if (node >= NN) return;
    int lane = threadIdx.x & 31;

    int do_relu = (out_ptr == nullptr);
    float* out = do_relu ? g_h : out_ptr;

    const float4 q4 = *(const float4*)(g_q + node * DD + lane * 4);

    float4 acc = make_float4(0.f, 0.f, 0.f, 0.f);
    float m = -1e30f, s = 0.f;

    int j = g_off[node];
    int end = g_off[node + 1];
    const float SC = 0.17677669529663689f;       // 1/sqrt(32)

    for (; j + 2 <= end; j += 2) {
        int s0 = g_csrc[j];
        int s1 = g_csrc[j + 1];
        const float4 k0 = *(const float4*)(g_k + s0 * DD + lane * 4);
        const float4 v0 = *(const float4*)(g_v + s0 * DD + lane * 4);
        const float4 k1 = *(const float4*)(g_k + s1 * DD + lane * 4);
        const float4 v1 = *(const float4*)(g_v + s1 * DD + lane * 4);

        float t0 = q4.x * k0.x + q4.y * k0.y + q4.z * k0.z + q4.w * k0.w;
        float t1 = q4.x * k1.x + q4.y * k1.y + q4.z * k1.z + q4.w * k1.w;
        t0 += __shfl_xor_sync(0xffffffffu, t0, 1);
        t1 += __shfl_xor_sync(0xffffffffu, t1, 1);
        t0 += __shfl_xor_sync(0xffffffffu, t0, 2);
        t1 += __shfl_xor_sync(0xffffffffu, t1, 2);
        t0 += __shfl_xor_sync(0xffffffffu, t0, 4);
        t1 += __shfl_xor_sync(0xffffffffu, t1, 4);

        float l0 = t0 * SC;
        float l1 = t1 * SC;
        float nm = fmaxf(m, fmaxf(l0, l1));
        float fac = __expf(m - nm);
        float e0 = __expf(l0 - nm);
        float e1 = __expf(l1 - nm);
        s = s * fac + e0 + e1;
        acc.x = acc.x * fac + v0.x * e0 + v1.x * e1;
        acc.y = acc.y * fac + v0.y * e0 + v1.y * e1;
        acc.z = acc.z * fac + v0.z * e0 + v1.z * e1;
        acc.w = acc.w * fac + v0.w * e0 + v1.w * e1;
        m = nm;
    }
    if (j < end) {
        int s0 = g_csrc[j];
        const float4 k0 = *(const float4*)(g_k + s0 * DD + lane * 4);
        const float4 v0 = *(const float4*)(g_v + s0 * DD + lane * 4);
        float t0 = q4.x * k0.x + q4.y * k0.y + q4.z * k0.z + q4.w * k0.w;
        t0 += __shfl_xor_sync(0xffffffffu, t0, 1);
        t0 += __shfl_xor_sync(0xffffffffu, t0, 2);
        t0 += __shfl_xor_sync(0xffffffffu, t0, 4);
        float l0 = t0 * SC;
        float nm = fmaxf(m, l0);
        float fac = __expf(m - nm);
        float e0 = __expf(l0 - nm);
        s = s * fac + e0;
        acc.x = acc.x * fac + v0.x * e0;
        acc.y = acc.y * fac + v0.y * e0;
        acc.z = acc.z * fac + v0.z * e0;
        acc.w = acc.w * fac + v0.w * e0;
        m = nm;
    }

    float inv = 1.f / (s + 1e-16f);
    const float4 sk = *(const float4*)(g_skip + node * DD + lane * 4);
    float4 o;
    o.x = acc.x * inv + sk.x;
    o.y = acc.y * inv + sk.y;
    o.z = acc.z * inv + sk.z;
    o.w = acc.w * inv + sk.w;
    if (do_relu) {
        o.x = fmaxf(o.x, 0.f);
        o.y = fmaxf(o.y, 0.f);
        o.z = fmaxf(o.z, 0.f);
        o.w = fmaxf(o.w, 0.f);
    }
    *(float4*)(out + node * DD + lane * 4) = o;
}

// ---------------- launch ----------------------------------------------------
extern "C" void kernel_launch(void* const* d_in, const int* in_sizes, int n_in,
                              void* d_out, int out_size) {
    const float* x = (const float*)d_in[0];
    const void* ei = d_in[1];    // int32 or int64 — detected on device
    float* out = (float*)d_out;

    const int NB_SCAN1 = (NN + 511) / 512;       // 98
    const int PROJ_GRID = (NN + 63) / 64;        // 782
    const int ATTN_GRID = (NN + 7) / 8;          // 6250

    k_detect_zero<<<(NN + 255) / 256, 256>>>((const int*)ei);      // 0
    k_wrepack<<<512, 256>>>(                                       // 1
        (const float*)d_in[2], (const float*)d_in[4],
        (const float*)d_in[6], (const float*)d_in[8],
        (const float*)d_in[10], (const float*)d_in[12],
        (const float*)d_in[14], (const float*)d_in[16]);
    k_hist<<<(EE + 255) / 256, 256>>>(ei);                         // 2
    k_proj<<<PROJ_GRID, 128>>>(x, 0,                               // 3 (profiled)
        (const float*)d_in[3], (const float*)d_in[5],
        (const float*)d_in[7], (const float*)d_in[9]);
    k_scan1<<<NB_SCAN1, 512>>>();                                  // 4
    k_scan2<<<1, 128>>>(NB_SCAN1);                                 // 5
    k_scan3<<<(NN + 255) / 256, 256>>>();                          // 6
    k_scatter<<<(EE + 255) / 256, 256>>>(ei);                      // 7
    k_attn<<<ATTN_GRID, 256>>>(nullptr);                           // 8: g_h + relu
    k_proj<<<PROJ_GRID, 128>>>(nullptr, 4,                         // 9
        (const float*)d_in[11], (const float*)d_in[13],
        (const float*)d_in[15], (const float*)d_in[17]);
    k_attn<<<ATTN_GRID, 256>>>(out);                               // 10
}